// round 9
// baseline (speedup 1.0000x reference)
#include <cuda_runtime.h>

#define BB   32
#define CC   16
#define RES  128
#define NANG 64

// Weighted image, plain batch-innermost layout: g_W[(y*128+x)*32 + b]
__device__ float g_W[RES * RES * BB];

// ---------------------------------------------------------------------------
// packed f32x2 helpers (sm_103a)
// ---------------------------------------------------------------------------
typedef unsigned long long u64;
__device__ __forceinline__ u64 pk2(float v) {
    u64 r; asm("mov.b64 %0,{%1,%1};" : "=l"(r) : "f"(v)); return r;
}
__device__ __forceinline__ u64 f2fma(u64 a, u64 b, u64 c) {
    u64 d; asm("fma.rn.f32x2 %0,%1,%2,%3;" : "=l"(d) : "l"(a), "l"(b), "l"(c)); return d;
}
__device__ __forceinline__ float2 up2(u64 v) {
    float2 f; asm("mov.b64 {%0,%1},%2;" : "=f"(f.x), "=f"(f.y) : "l"(v)); return f;
}

// ---------------------------------------------------------------------------
// Kernel 1: channel-weighted image -> (y,x,b) layout, coalesced both phases.
// ---------------------------------------------------------------------------
__global__ __launch_bounds__(1024) void k_weight(const float* __restrict__ x,
                                                 const float* __restrict__ w) {
    __shared__ float S[RES][33];
    const int y = blockIdx.x, tid = threadIdx.x;
    float wv[CC];
#pragma unroll
    for (int c = 0; c < CC; c++) wv[c] = __ldg(&w[c]);

    const int xi = tid & 127, b0 = tid >> 7;
#pragma unroll
    for (int k = 0; k < 4; k++) {
        int b = b0 + k * 8;
        const float* px = x + ((size_t)(b * CC) * RES + y) * RES + xi;
        float s = 0.f;
#pragma unroll
        for (int c = 0; c < CC; c++)
            s = fmaf(wv[c], __ldg(&px[(size_t)c * RES * RES]), s);
        S[xi][b] = s;
    }
    __syncthreads();
    const int b = tid & 31, xg = tid >> 5;
#pragma unroll
    for (int k = 0; k < 4; k++) {
        int x2 = xg + k * 32;
        g_W[(y * 128 + x2) * 32 + b] = S[x2][b];
    }
}

// ---------------------------------------------------------------------------
// Interval helper: intersect {j : lo < P + Q*j < hi} into [jmn, jmx].
// ---------------------------------------------------------------------------
__device__ __forceinline__ void isect(float P, float Q, float lo, float hi,
                                      float& jmn, float& jmx) {
    if (Q == 0.f) {
        if (P <= lo || P >= hi) { jmn = 1e9f; jmx = -1e9f; }
    } else {
        float t0 = (lo - P) / Q, t1 = (hi - P) / Q;
        jmn = fmaxf(jmn, fminf(t0, t1));
        jmx = fminf(jmx, fmaxf(t0, t1));
    }
}

__device__ __forceinline__ int wmax(int v) {
#pragma unroll
    for (int o = 16; o; o >>= 1) v = max(v, __shfl_xor_sync(0xffffffffu, v, o));
    return v;
}
__device__ __forceinline__ int wmin(int v) {
#pragma unroll
    for (int o = 16; o; o >>= 1) v = min(v, __shfl_xor_sync(0xffffffffu, v, o));
    return v;
}

// ---------------------------------------------------------------------------
// Kernel 2: radon. Block = 128 threads = 4 warps = 1 row-quad x 4 j-segments.
// Warp lanes: sub = lane>>3 (row in quad), q = lane&7 (batch quad 4q..4q+3).
// Each warp sums its j-segment; 4 partials reduced in smem in fixed order.
// grid (32, 64) = (row-quads, angles); center quads scheduled first.
// __launch_bounds__(128,10): cap regs ~48 -> 40 warps/SM (62.5% occ).
// ---------------------------------------------------------------------------
__global__ __launch_bounds__(128, 10) void k_radon(const float* __restrict__ angles,
                                                   const float* __restrict__ bias,
                                                   float* __restrict__ out) {
    __shared__ float4 red[4][32];

    const int tid  = threadIdx.x;
    const int lane = tid & 31;
    const int seg  = tid >> 5;                      // j-segment 0..3
    const int sub  = lane >> 3;                     // row within quad
    const int q    = lane & 7;                      // batch quad: b = 4q..4q+3
    const int bx   = blockIdx.x;                    // 0..31
    const int quad = (bx & 1) ? (16 + (bx >> 1)) : (15 - (bx >> 1));
    const int i    = quad * 4 + sub;                // detector row
    const int a    = blockIdx.y;                    // angle

    const float theta = __ldg(&angles[a]);
    const float c = cosf(theta), s = sinf(theta);
    const float ci = (float)i - 63.5f;

    // xs(j) = ax - s*cj,  ys(j) = ay + c*cj,  cj = j - 63.5
    const float ax = fmaf(ci, c, 63.5f);
    const float ay = fmaf(ci, s, 63.5f);
    const float A  = fmaf(63.5f, s, ax), Bq = -s;
    const float Cq = fmaf(-63.5f, c, ay), Dq = c;

    // Loose window (any tap possibly nonzero) per row
    float jmn = 0.f, jmx = 127.f;
    isect(A, Bq, -1.f, 128.f, jmn, jmx);
    isect(Cq, Dq, -1.f, 128.f, jmn, jmx);
    jmn = fminf(fmaxf(jmn, 0.f), 127.f);
    jmx = fminf(fmaxf(jmx, 0.f), 127.f);
    int jA, jB;
    if (jmn > jmx) { jA = 0; jB = -1; }
    else { jA = max(0, (int)floorf(jmn) - 1); jB = min(127, (int)ceilf(jmx) + 1); }

    // Strict interior window (all 4 taps in-bounds) per row
    float jmn2 = 0.f, jmx2 = 127.f;
    isect(A, Bq, 0.01f, 126.99f, jmn2, jmx2);
    isect(Cq, Dq, 0.01f, 126.99f, jmn2, jmx2);
    jmn2 = fminf(fmaxf(jmn2, 0.f), 127.f);
    jmx2 = fminf(fmaxf(jmx2, 0.f), 127.f);
    int jC, jD;
    if (jmn2 > jmx2) { jC = jB + 1; jD = jB; }
    else {
        jC = max(jA, (int)ceilf(jmn2) + 1);
        jD = min(jB, (int)floorf(jmx2) - 1);
        if (jC > jD) { jC = jB + 1; jD = jB; }
    }

    // Warp-union windows over the 4 rows of this quad. Masked path is exact
    // (zero weights) for ANY j, so widening to the union preserves semantics.
    const int jAw = wmin(jA), jBw = wmax(jB);
    const int jCw = wmax(jC);
    int jDw = wmin(jD);
    if (jDw < jCw - 1) jDw = jCw - 1;               // keep jCw <= jDw+1

    // This warp's segment of the union window [jAw, jBw]
    const int len   = jBw - jAw + 1;                // may be <= 0 (empty)
    const int segLo = jAw + (seg * len) / 4;
    const int segHi = jAw + ((seg + 1) * len) / 4 - 1;

    // Packed accumulators: A/B = row-iy contribution (batch pairs 01 / 23),
    // C/D = row-iy+1 contribution.
    u64 accA = 0, accB = 0, accC = 0, accD = 0;
    float m0 = 0.f, m1 = 0.f, m2 = 0.f, m3 = 0.f;   // masked-path accumulators

    const float4* W4 = (const float4*)g_W;

    // Exact masked step (reference semantics: clipped indices, zeroed OOB taps)
    auto masked = [&](int j) {
        float cjm = (float)j - 63.5f;
        float xs = fmaf(-s, cjm, ax);
        float ys = fmaf(c, cjm, ay);
        int ix = __float2int_rd(xs), iy = __float2int_rd(ys);
        float wx = xs - (float)ix, wy = ys - (float)iy;
        float u = 1.f - wx, v = 1.f - wy;
        float mx0 = (ix >= 0 && ix < 128) ? 1.f : 0.f;
        float mx1 = (ix >= -1 && ix < 127) ? 1.f : 0.f;
        float my0 = (iy >= 0 && iy < 128) ? 1.f : 0.f;
        float my1 = (iy >= -1 && iy < 127) ? 1.f : 0.f;
        int cx0 = min(max(ix, 0), 127), cx1 = min(max(ix + 1, 0), 127);
        int cy0 = min(max(iy, 0), 127), cy1 = min(max(iy + 1, 0), 127);
        float w00 = (v * my0) * (u * mx0),  w01 = (v * my0) * (wx * mx1);
        float w10 = (wy * my1) * (u * mx0), w11 = (wy * my1) * (wx * mx1);
        float4 v00 = __ldg(&W4[(cy0 * 128 + cx0) * 8 + q]);
        float4 v01 = __ldg(&W4[(cy0 * 128 + cx1) * 8 + q]);
        float4 v10 = __ldg(&W4[(cy1 * 128 + cx0) * 8 + q]);
        float4 v11 = __ldg(&W4[(cy1 * 128 + cx1) * 8 + q]);
        m0 = fmaf(w00, v00.x, fmaf(w01, v01.x, fmaf(w10, v10.x, fmaf(w11, v11.x, m0))));
        m1 = fmaf(w00, v00.y, fmaf(w01, v01.y, fmaf(w10, v10.y, fmaf(w11, v11.y, m1))));
        m2 = fmaf(w00, v00.z, fmaf(w01, v01.z, fmaf(w10, v10.z, fmaf(w11, v11.z, m2))));
        m3 = fmaf(w00, v00.w, fmaf(w01, v01.w, fmaf(w10, v10.w, fmaf(w11, v11.w, m3))));
    };

    // Segment partition: head (masked, j<jCw) | fast [jCw,jDw] | tail (j>jDw)
    const int h1 = min(segHi, jCw - 1);
#pragma unroll 1
    for (int j = segLo; j <= h1; j++) masked(j);

    const int f0 = max(segLo, jCw), f1 = min(segHi, jDw);
    if (f0 <= f1) {
        const ulonglong2* Wq = (const ulonglong2*)g_W + q;   // batch-quad base
        const u64 M1 = pk2(-1.f);
        float cj = (float)f0 - 63.5f;                // exact; += 1.0f stays exact
#pragma unroll 4
        for (int j = f0; j <= f1; j++) {
            float xs = fmaf(-s, cj, ax);
            float ys = fmaf(c, cj, ay);
            cj += 1.0f;
            float fx = floorf(xs), fy = floorf(ys);
            float wx = xs - fx,    wy = ys - fy;
            int idx = __float2int_rn(fmaf(fy, 128.f, fx));   // iy*128+ix, exact
            const ulonglong2* p = Wq + ((long)idx << 3);
            u64 wx2 = pk2(wx);
            // row iy: consume taps immediately (short live ranges)
            {
                ulonglong2 t00 = __ldg(p);                   // (iy  ,ix  )
                ulonglong2 t01 = __ldg(p + 8);               // (iy  ,ix+1)
                u64 v2 = pk2(1.f - wy);
                u64 s0a = f2fma(wx2, f2fma(t00.x, M1, t01.x), t00.x);
                u64 s0b = f2fma(wx2, f2fma(t00.y, M1, t01.y), t00.y);
                accA = f2fma(v2, s0a, accA);
                accB = f2fma(v2, s0b, accB);
            }
            // row iy+1
            {
                ulonglong2 t10 = __ldg(p + 1024);            // (iy+1,ix  )
                ulonglong2 t11 = __ldg(p + 1032);            // (iy+1,ix+1)
                u64 wy2 = pk2(wy);
                u64 s1a = f2fma(wx2, f2fma(t10.x, M1, t11.x), t10.x);
                u64 s1b = f2fma(wx2, f2fma(t10.y, M1, t11.y), t10.y);
                accC = f2fma(wy2, s1a, accC);
                accD = f2fma(wy2, s1b, accD);
            }
        }
    }

    const int t0 = max(segLo, jDw + 1);
#pragma unroll 1
    for (int j = t0; j <= segHi; j++) masked(j);

    // Per-warp partial results -> smem
    float2 Af = up2(accA), Bf = up2(accB), Cf = up2(accC), Df = up2(accD);
    float4 part;
    part.x = (Af.x + Cf.x) + m0;
    part.y = (Af.y + Cf.y) + m1;
    part.z = (Bf.x + Df.x) + m2;
    part.w = (Bf.y + Df.y) + m3;
    red[seg][lane] = part;
    __syncthreads();

    // Reduce 4 segments in fixed order (deterministic) and store.
    if (tid < 32) {
        const int qq = tid & 7, sb = tid >> 3;
        float4 r = red[0][tid];
#pragma unroll
        for (int ss = 1; ss < 4; ss++) {
            float4 p = red[ss][tid];
            r.x += p.x; r.y += p.y; r.z += p.z; r.w += p.w;
        }
        const float bv = __ldg(&bias[0]);
        const int ii = quad * 4 + sb;
        const int b0 = 4 * qq;
        out[((b0 + 0) * NANG + a) * RES + ii] = r.x + bv;
        out[((b0 + 1) * NANG + a) * RES + ii] = r.y + bv;
        out[((b0 + 2) * NANG + a) * RES + ii] = r.z + bv;
        out[((b0 + 3) * NANG + a) * RES + ii] = r.w + bv;
    }
}

// ---------------------------------------------------------------------------
extern "C" void kernel_launch(void* const* d_in, const int* in_sizes, int n_in,
                              void* d_out, int out_size) {
    const float* x      = (const float*)d_in[0];   // (32,16,128,128) f32
    const float* angles = (const float*)d_in[1];   // (64,)           f32
    const float* conv_w = (const float*)d_in[2];   // (1,16,1,1)      f32
    const float* conv_b = (const float*)d_in[3];   // (1,)            f32
    float* out = (float*)d_out;                    // (32,1,64,128)   f32

    k_weight<<<RES, 1024>>>(x, conv_w);
    dim3 g(32, NANG);
    k_radon<<<g, 128>>>(angles, conv_b, out);
}

// round 10
// speedup vs baseline: 1.1244x; 1.1244x over previous
#include <cuda_runtime.h>

#define BB   32
#define CC   16
#define RES  128
#define NANG 64

// Weighted image, batch-innermost: g_W[(y*128+x)*32 + b]
__device__ float g_W[RES * RES * BB];
// Per-angle trig and per-(angle,quad) j-windows, computed in k_weight.
__device__ float2 g_trig[NANG];
__device__ int4   g_win[NANG * 32];

// ---------------------------------------------------------------------------
// packed f32x2 helpers (sm_103a)
// ---------------------------------------------------------------------------
typedef unsigned long long u64;
__device__ __forceinline__ u64 pk2(float v) {
    u64 r; asm("mov.b64 %0,{%1,%1};" : "=l"(r) : "f"(v)); return r;
}
__device__ __forceinline__ u64 f2fma(u64 a, u64 b, u64 c) {
    u64 d; asm("fma.rn.f32x2 %0,%1,%2,%3;" : "=l"(d) : "l"(a), "l"(b), "l"(c)); return d;
}
__device__ __forceinline__ float2 up2(u64 v) {
    float2 f; asm("mov.b64 {%0,%1},%2;" : "=f"(f.x), "=f"(f.y) : "l"(v)); return f;
}

// ---------------------------------------------------------------------------
// Interval helper: intersect {j : lo < P + Q*j < hi} into [jmn, jmx].
// ---------------------------------------------------------------------------
__device__ __forceinline__ void isect(float P, float Q, float lo, float hi,
                                      float& jmn, float& jmx) {
    if (Q == 0.f) {
        if (P <= lo || P >= hi) { jmn = 1e9f; jmx = -1e9f; }
    } else {
        float t0 = (lo - P) / Q, t1 = (hi - P) / Q;
        jmn = fmaxf(jmn, fminf(t0, t1));
        jmx = fminf(jmx, fmaxf(t0, t1));
    }
}

// ---------------------------------------------------------------------------
// Kernel 1: channel-weighted image -> (y,x,b) layout; ALSO precomputes trig
// + j-windows for all (angle, row-quad) pairs in spare threads of blocks 0-63.
// ---------------------------------------------------------------------------
__global__ __launch_bounds__(1024) void k_weight(const float* __restrict__ x,
                                                 const float* __restrict__ w,
                                                 const float* __restrict__ angles) {
    __shared__ float S[RES][33];
    const int y = blockIdx.x, tid = threadIdx.x;

    // ---- window/trig precompute: 32 threads in each of blocks 0..63 ----
    if (y < NANG && tid >= 992) {
        const int a = y, quad = tid - 992;
        const float theta = __ldg(&angles[a]);
        const float c = cosf(theta), s = sinf(theta);
        if (quad == 0) g_trig[a] = make_float2(c, s);

        int jAw = 1 << 30, jBw = -(1 << 30), jCw = -(1 << 30), jDw = 1 << 30;
#pragma unroll 1
        for (int r = 0; r < 4; r++) {
            const int i = quad * 4 + r;
            const float ci = (float)i - 63.5f;
            const float ax = fmaf(ci, c, 63.5f);
            const float ay = fmaf(ci, s, 63.5f);
            const float A  = fmaf(63.5f, s, ax), Bq = -s;
            const float Cq = fmaf(-63.5f, c, ay), Dq = c;

            float jmn = 0.f, jmx = 127.f;
            isect(A, Bq, -1.f, 128.f, jmn, jmx);
            isect(Cq, Dq, -1.f, 128.f, jmn, jmx);
            jmn = fminf(fmaxf(jmn, 0.f), 127.f);
            jmx = fminf(fmaxf(jmx, 0.f), 127.f);
            int jA, jB;
            if (jmn > jmx) { jA = 0; jB = -1; }
            else { jA = max(0, (int)floorf(jmn) - 1); jB = min(127, (int)ceilf(jmx) + 1); }

            float jmn2 = 0.f, jmx2 = 127.f;
            isect(A, Bq, 0.01f, 126.99f, jmn2, jmx2);
            isect(Cq, Dq, 0.01f, 126.99f, jmn2, jmx2);
            jmn2 = fminf(fmaxf(jmn2, 0.f), 127.f);
            jmx2 = fminf(fmaxf(jmx2, 0.f), 127.f);
            int jC, jD;
            if (jmn2 > jmx2) { jC = jB + 1; jD = jB; }
            else {
                jC = max(jA, (int)ceilf(jmn2) + 1);
                jD = min(jB, (int)floorf(jmx2) - 1);
                if (jC > jD) { jC = jB + 1; jD = jB; }
            }
            jAw = min(jAw, jA); jBw = max(jBw, jB);
            jCw = max(jCw, jC); jDw = min(jDw, jD);
        }
        if (jDw < jCw - 1) jDw = jCw - 1;
        g_win[a * 32 + quad] = make_int4(jAw, jBw, jCw, jDw);
    }

    // ---- weighted image: thread = (batch b, 4 x-positions) ----
    float wv[CC];
#pragma unroll
    for (int c = 0; c < CC; c++) wv[c] = __ldg(&w[c]);

    const int xi4 = tid & 31;                       // float4 index along x
    const int b   = tid >> 5;                       // batch 0..31
    const float4* px = (const float4*)(x + ((size_t)(b * CC)) * RES * RES
                                         + (size_t)y * RES) + xi4;
    float4 acc = make_float4(0.f, 0.f, 0.f, 0.f);
#pragma unroll
    for (int c = 0; c < CC; c++) {
        float4 t = __ldg(px + (size_t)c * (RES * RES / 4));
        acc.x = fmaf(wv[c], t.x, acc.x);
        acc.y = fmaf(wv[c], t.y, acc.y);
        acc.z = fmaf(wv[c], t.z, acc.z);
        acc.w = fmaf(wv[c], t.w, acc.w);
    }
    S[4 * xi4 + 0][b] = acc.x;
    S[4 * xi4 + 1][b] = acc.y;
    S[4 * xi4 + 2][b] = acc.z;
    S[4 * xi4 + 3][b] = acc.w;
    __syncthreads();

    // write phase: lanes = consecutive b -> coalesced STG.32
    const int bb = tid & 31, xg = tid >> 5;
#pragma unroll
    for (int k = 0; k < 4; k++) {
        int x2 = xg + k * 32;
        g_W[(y * 128 + x2) * 32 + bb] = S[x2][bb];
    }
}

// ---------------------------------------------------------------------------
// Kernel 2: radon. Block = 128 threads = 4 warps = 1 row-quad x 4 j-segments.
// Prologue is 2 table loads; all window math precomputed. Lanes: sub=lane>>3
// (row in quad), q=lane&7 (batch quad 4q..4q+3). Deterministic smem reduce.
// grid (32, 64); center quads scheduled first.
// ---------------------------------------------------------------------------
__global__ __launch_bounds__(128) void k_radon(const float* __restrict__ bias,
                                               float* __restrict__ out) {
    __shared__ float4 red[4][32];

    const int tid  = threadIdx.x;
    const int lane = tid & 31;
    const int seg  = tid >> 5;                      // j-segment 0..3
    const int sub  = lane >> 3;                     // row within quad
    const int q    = lane & 7;                      // batch quad: b = 4q..4q+3
    const int bx   = blockIdx.x;                    // 0..31
    const int quad = (bx & 1) ? (16 + (bx >> 1)) : (15 - (bx >> 1));
    const int i    = quad * 4 + sub;                // detector row
    const int a    = blockIdx.y;                    // angle

    const float2 cs = g_trig[a];
    const float c = cs.x, s = cs.y;
    const int4 wn = g_win[a * 32 + quad];           // jAw, jBw, jCw, jDw
    const float ci = (float)i - 63.5f;
    const float ax = fmaf(ci, c, 63.5f);
    const float ay = fmaf(ci, s, 63.5f);

    // This warp's segment of the union window [jAw, jBw]
    const int len   = wn.y - wn.x + 1;
    const int segLo = wn.x + (seg * len) / 4;
    const int segHi = wn.x + ((seg + 1) * len) / 4 - 1;
    const int jCw = wn.z, jDw = wn.w;

    u64 accA = 0, accB = 0, accC = 0, accD = 0;
    float m0 = 0.f, m1 = 0.f, m2 = 0.f, m3 = 0.f;

    const float4* W4 = (const float4*)g_W;

    // Exact masked step (reference semantics: clipped indices, zeroed OOB taps)
    auto masked = [&](int j) {
        float cjm = (float)j - 63.5f;
        float xs = fmaf(-s, cjm, ax);
        float ys = fmaf(c, cjm, ay);
        int ix = __float2int_rd(xs), iy = __float2int_rd(ys);
        float wx = xs - (float)ix, wy = ys - (float)iy;
        float u = 1.f - wx, v = 1.f - wy;
        float mx0 = (ix >= 0 && ix < 128) ? 1.f : 0.f;
        float mx1 = (ix >= -1 && ix < 127) ? 1.f : 0.f;
        float my0 = (iy >= 0 && iy < 128) ? 1.f : 0.f;
        float my1 = (iy >= -1 && iy < 127) ? 1.f : 0.f;
        int cx0 = min(max(ix, 0), 127), cx1 = min(max(ix + 1, 0), 127);
        int cy0 = min(max(iy, 0), 127), cy1 = min(max(iy + 1, 0), 127);
        float w00 = (v * my0) * (u * mx0),  w01 = (v * my0) * (wx * mx1);
        float w10 = (wy * my1) * (u * mx0), w11 = (wy * my1) * (wx * mx1);
        float4 v00 = __ldg(&W4[(cy0 * 128 + cx0) * 8 + q]);
        float4 v01 = __ldg(&W4[(cy0 * 128 + cx1) * 8 + q]);
        float4 v10 = __ldg(&W4[(cy1 * 128 + cx0) * 8 + q]);
        float4 v11 = __ldg(&W4[(cy1 * 128 + cx1) * 8 + q]);
        m0 = fmaf(w00, v00.x, fmaf(w01, v01.x, fmaf(w10, v10.x, fmaf(w11, v11.x, m0))));
        m1 = fmaf(w00, v00.y, fmaf(w01, v01.y, fmaf(w10, v10.y, fmaf(w11, v11.y, m1))));
        m2 = fmaf(w00, v00.z, fmaf(w01, v01.z, fmaf(w10, v10.z, fmaf(w11, v11.z, m2))));
        m3 = fmaf(w00, v00.w, fmaf(w01, v01.w, fmaf(w10, v10.w, fmaf(w11, v11.w, m3))));
    };

    // head (masked) | fast [jCw,jDw] | tail (masked), clipped to this segment
    const int h1 = min(segHi, jCw - 1);
#pragma unroll 1
    for (int j = segLo; j <= h1; j++) masked(j);

    const int f0 = max(segLo, jCw), f1 = min(segHi, jDw);
    if (f0 <= f1) {
        const ulonglong2* Wq = (const ulonglong2*)g_W + q;
        const u64 M1 = pk2(-1.f);
        float cj = (float)f0 - 63.5f;               // exact; += 1.0f stays exact
#pragma unroll 4
        for (int j = f0; j <= f1; j++) {
            float xs = fmaf(-s, cj, ax);
            float ys = fmaf(c, cj, ay);
            cj += 1.0f;
            float fx = floorf(xs), fy = floorf(ys);
            float wx = xs - fx,    wy = ys - fy;
            int idx = __float2int_rn(fmaf(fy, 128.f, fx));   // iy*128+ix, exact
            const ulonglong2* p = Wq + ((long)idx << 3);
            u64 wx2 = pk2(wx);
            {
                ulonglong2 t00 = __ldg(p);                   // (iy  ,ix  )
                ulonglong2 t01 = __ldg(p + 8);               // (iy  ,ix+1)
                u64 v2 = pk2(1.f - wy);
                u64 s0a = f2fma(wx2, f2fma(t00.x, M1, t01.x), t00.x);
                u64 s0b = f2fma(wx2, f2fma(t00.y, M1, t01.y), t00.y);
                accA = f2fma(v2, s0a, accA);
                accB = f2fma(v2, s0b, accB);
            }
            {
                ulonglong2 t10 = __ldg(p + 1024);            // (iy+1,ix  )
                ulonglong2 t11 = __ldg(p + 1032);            // (iy+1,ix+1)
                u64 wy2 = pk2(wy);
                u64 s1a = f2fma(wx2, f2fma(t10.x, M1, t11.x), t10.x);
                u64 s1b = f2fma(wx2, f2fma(t10.y, M1, t11.y), t10.y);
                accC = f2fma(wy2, s1a, accC);
                accD = f2fma(wy2, s1b, accD);
            }
        }
    }

    const int t0 = max(segLo, jDw + 1);
#pragma unroll 1
    for (int j = t0; j <= segHi; j++) masked(j);

    float2 Af = up2(accA), Bf = up2(accB), Cf = up2(accC), Df = up2(accD);
    float4 part;
    part.x = (Af.x + Cf.x) + m0;
    part.y = (Af.y + Cf.y) + m1;
    part.z = (Bf.x + Df.x) + m2;
    part.w = (Bf.y + Df.y) + m3;
    red[seg][lane] = part;
    __syncthreads();

    // Reduce 4 segments in fixed order (deterministic) and store.
    if (tid < 32) {
        const int qq = tid & 7, sb = tid >> 3;
        float4 r = red[0][tid];
#pragma unroll
        for (int ss = 1; ss < 4; ss++) {
            float4 p = red[ss][tid];
            r.x += p.x; r.y += p.y; r.z += p.z; r.w += p.w;
        }
        const float bv = __ldg(&bias[0]);
        const int ii = quad * 4 + sb;
        const int b0 = 4 * qq;
        out[((b0 + 0) * NANG + a) * RES + ii] = r.x + bv;
        out[((b0 + 1) * NANG + a) * RES + ii] = r.y + bv;
        out[((b0 + 2) * NANG + a) * RES + ii] = r.z + bv;
        out[((b0 + 3) * NANG + a) * RES + ii] = r.w + bv;
    }
}

// ---------------------------------------------------------------------------
extern "C" void kernel_launch(void* const* d_in, const int* in_sizes, int n_in,
                              void* d_out, int out_size) {
    const float* x      = (const float*)d_in[0];   // (32,16,128,128) f32
    const float* angles = (const float*)d_in[1];   // (64,)           f32
    const float* conv_w = (const float*)d_in[2];   // (1,16,1,1)      f32
    const float* conv_b = (const float*)d_in[3];   // (1,)            f32
    float* out = (float*)d_out;                    // (32,1,64,128)   f32

    k_weight<<<RES, 1024>>>(x, conv_w, angles);
    dim3 g(32, NANG);
    k_radon<<<g, 128>>>(conv_b, out);
}